// round 9
// baseline (speedup 1.0000x reference)
#include <cuda_runtime.h>
#include <math.h>
#include <stdint.h>

#define B 2048
#define N 128
#define D 512
#define BD (B * D)
#define NW 4             // warps per CTA in fuse kernel
#define NT (NW * 32)     // 128 threads

// 8 MB scratch for cw = content @ cow, rows interleaved: row 2b = text[b]@cow, 2b+1 = img[b]@cow
__device__ float g_cw[2 * B * D];

__device__ __forceinline__ float tanha(float x) {
    float y;
    asm("tanh.approx.f32 %0, %1;" : "=f"(y) : "f"(x));
    return y;
}
__device__ __forceinline__ float ex2(float x) {
    float y;
    asm("ex2.approx.f32 %0, %1;" : "=f"(y) : "f"(x));
    return y;
}
__device__ __forceinline__ uint32_t f2tf32(float x) {
    uint32_t r;
    asm("cvt.rna.tf32.f32 %0, %1;" : "=r"(r) : "f"(x));
    return r;
}
__device__ __forceinline__ void mma_tf32(float c[4], const uint32_t a[4], const uint32_t b[2]) {
    asm volatile(
        "mma.sync.aligned.m16n8k8.row.col.f32.tf32.tf32.f32 "
        "{%0,%1,%2,%3}, {%4,%5,%6,%7}, {%8,%9}, {%0,%1,%2,%3};"
        : "+f"(c[0]), "+f"(c[1]), "+f"(c[2]), "+f"(c[3])
        : "r"(a[0]), "r"(a[1]), "r"(a[2]), "r"(a[3]), "r"(b[0]), "r"(b[1]));
}
__device__ __forceinline__ void cp_async16(void* smem_dst, const void* gmem_src) {
    uint32_t s = (uint32_t)__cvta_generic_to_shared(smem_dst);
    asm volatile("cp.async.ca.shared.global [%0], [%1], 16;" :: "r"(s), "l"(gmem_src));
}
__device__ __forceinline__ void cp_commit() {
    asm volatile("cp.async.commit_group;");
}

// ---------------------------------------------------------------------------
// Kernel 1: cw[4096,512] = A[4096,512] @ cow[512,512] via tf32x3 mma.sync.
// Tile M=64 N=64 K=32; grid 512 CTAs; 128 thr (4 warps, 2x2 warp grid,
// 32x32 warp tile); 3-stage cp.async pipeline.
// ---------------------------------------------------------------------------
#define GM_KT 32
#define AST 36     // A row stride (floats): [m][k] padded
#define WST 68     // W row stride (floats): [k][n] padded
#define A_STAGE (64 * AST)
#define W_STAGE (GM_KT * WST)
#define NSTG 3
#define GEMM_SMEM_BYTES ((NSTG * A_STAGE + NSTG * W_STAGE) * 4)

__global__ __launch_bounds__(128) void gemm_cw_tf32(
    const float* __restrict__ text,
    const float* __restrict__ img,
    const float* __restrict__ cow)
{
    extern __shared__ float gsm[];
    float* As = gsm;                        // NSTG stages of [64][AST]
    float* Ws = gsm + NSTG * A_STAGE;       // NSTG stages of [GM_KT][WST]

    const int t = threadIdx.x;
    const int wid = t >> 5;
    const int lane = t & 31;
    const int warp_m = (wid & 1) * 32;
    const int warp_n = (wid >> 1) * 32;
    const int brow = blockIdx.y * 64;
    const int bcol = blockIdx.x * 64;
    const int g  = lane >> 2;   // 0..7
    const int tg = lane & 3;    // 0..3

    float c[2][4][4];
#pragma unroll
    for (int mi = 0; mi < 2; mi++)
#pragma unroll
        for (int ni = 0; ni < 4; ni++)
#pragma unroll
            for (int j = 0; j < 4; j++) c[mi][ni][j] = 0.f;

    // stage loader: A (64 x 32 floats, [m][k]) + W (32 x 64 floats, [k][n])
    auto load_stage = [&](int st, int k0) {
#pragma unroll
        for (int s = 0; s < 4; s++) {               // A: 512 x 16B / 128 thr
            int f = t + 128 * s;
            int r = f >> 3;
            int kk = (f & 7) * 4;
            int gr = brow + r;
            const float* src = ((gr & 1) ? img : text) + (size_t)(gr >> 1) * D + k0 + kk;
            cp_async16(&As[st * A_STAGE + r * AST + kk], src);
        }
#pragma unroll
        for (int s = 0; s < 4; s++) {               // W: 512 x 16B / 128 thr
            int f = t + 128 * s;
            int kk = f >> 4;
            int n = (f & 15) * 4;
            const float* src = cow + (size_t)(k0 + kk) * D + bcol + n;
            cp_async16(&Ws[st * W_STAGE + kk * WST + n], src);
        }
    };

    const int NKT = D / GM_KT;   // 16
    load_stage(0, 0); cp_commit();
    load_stage(1, GM_KT); cp_commit();

    for (int kt = 0; kt < NKT; kt++) {
        asm volatile("cp.async.wait_group 1;");
        __syncthreads();

        if (kt + 2 < NKT) {
            load_stage((kt + 2) % NSTG, (kt + 2) * GM_KT);
            cp_commit();
        }

        const float* Ab = As + (kt % NSTG) * A_STAGE;
        const float* Wb = Ws + (kt % NSTG) * W_STAGE;

#pragma unroll
        for (int k8 = 0; k8 < GM_KT; k8 += 8) {
            uint32_t ahi[2][4], alo[2][4];
#pragma unroll
            for (int mi = 0; mi < 2; mi++) {
                int r0 = warp_m + mi * 16;
                float av[4];
                av[0] = Ab[(r0 + g)     * AST + k8 + tg];
                av[1] = Ab[(r0 + 8 + g) * AST + k8 + tg];
                av[2] = Ab[(r0 + g)     * AST + k8 + tg + 4];
                av[3] = Ab[(r0 + 8 + g) * AST + k8 + tg + 4];
#pragma unroll
                for (int j = 0; j < 4; j++) {
                    uint32_t h = f2tf32(av[j]);
                    ahi[mi][j] = h;
                    alo[mi][j] = __float_as_uint(av[j] - __uint_as_float(h));
                }
            }
            uint32_t bhi[4][2], blo[4][2];
#pragma unroll
            for (int ni = 0; ni < 4; ni++) {
                int n0 = warp_n + ni * 8;
                float bv[2];
                bv[0] = Wb[(k8 + tg)     * WST + n0 + g];
                bv[1] = Wb[(k8 + tg + 4) * WST + n0 + g];
#pragma unroll
                for (int j = 0; j < 2; j++) {
                    uint32_t h = f2tf32(bv[j]);
                    bhi[ni][j] = h;
                    blo[ni][j] = __float_as_uint(bv[j] - __uint_as_float(h));
                }
            }
#pragma unroll
            for (int mi = 0; mi < 2; mi++)
#pragma unroll
                for (int ni = 0; ni < 4; ni++) {
                    mma_tf32(c[mi][ni], alo[mi], bhi[ni]);
                    mma_tf32(c[mi][ni], ahi[mi], blo[ni]);
                    mma_tf32(c[mi][ni], ahi[mi], bhi[ni]);
                }
        }
        __syncthreads();
    }

    // Store C
#pragma unroll
    for (int mi = 0; mi < 2; mi++)
#pragma unroll
        for (int ni = 0; ni < 4; ni++) {
            int row = brow + warp_m + mi * 16 + g;
            int col = bcol + warp_n + ni * 8 + 2 * tg;
            float2 v0 = make_float2(c[mi][ni][0], c[mi][ni][1]);
            float2 v1 = make_float2(c[mi][ni][2], c[mi][ni][3]);
            *reinterpret_cast<float2*>(&g_cw[(size_t)row * D + col]) = v0;
            *reinterpret_cast<float2*>(&g_cw[(size_t)(row + 8) * D + col]) = v1;
        }
}

// Dynamic SMEM layout for fuse kernel (floats)
#define OFF_CW0  0
#define OFF_CW1  (OFF_CW0 + D)
#define OFF_C0   (OFF_CW1 + D)
#define OFF_C1   (OFF_C0 + D)
#define OFF_BUFC (OFF_C1 + D)              // NW*D : per-warp aC
#define OFF_BA0  (OFF_BUFC + NW * D)       // NW*D : per-warp aA0
#define OFF_BA1  (OFF_BA0 + NW * D)        // NW*D : per-warp aA1
#define OFF_SS   (OFF_BA1 + NW * D)        // NW
#define OFF_R0   (OFF_SS + NW)             // NW
#define OFF_R1   (OFF_R0 + NW)             // NW
#define SMEM_FLOATS (OFF_R1 + NW)
#define SMEM_BYTES  (SMEM_FLOATS * 4)

// ---------------------------------------------------------------------------
// Kernel 2: one CTA (4 warps, 128 thr, <=128 regs, 4 CTAs/SM) per sample.
// Warp w processes row PAIRS (n, n+NW): the cw0/cw1/c0/c1 SMEM reads are
// shared across the pair, halving L1 wavefront traffic per row.
// No prefetch buffer (16 warps/SM hide latency). No atomics.
// Branchless unshifted softmax (|logit| <= ||W_co||_1 ~ 18 fits fp32 exp).
// ---------------------------------------------------------------------------
__global__ __launch_bounds__(NT, 4) void fuse_kernel(
    const float* __restrict__ text,
    const float* __restrict__ img,
    const float* __restrict__ comment,
    const int*   __restrict__ comment_num,
    const float* __restrict__ W_ca,
    const float* __restrict__ W_co,
    float* __restrict__ out)
{
    extern __shared__ float sm[];
    const int b = blockIdx.x;
    const int tid = threadIdx.x;
    const int w = tid >> 5;
    const int lane = tid & 31;

    for (int d = tid; d < D; d += NT) {
        sm[OFF_CW0 + d] = g_cw[(size_t)(2 * b) * D + d];
        sm[OFF_CW1 + d] = g_cw[(size_t)(2 * b + 1) * D + d];
        sm[OFF_C0 + d]  = text[(size_t)b * D + d];
        sm[OFF_C1 + d]  = img[(size_t)b * D + d];
    }
    __syncthreads();

    const float LOG2E = 1.4426950408889634f;
    float4 wr[4];
#pragma unroll
    for (int j = 0; j < 4; j++) {
        float4 wv = __ldg(&reinterpret_cast<const float4*>(W_co)[lane + 32 * j]);
        wr[j] = make_float4(wv.x * LOG2E, wv.y * LOG2E, wv.z * LOG2E, wv.w * LOG2E);
    }

    const int num = comment_num[b];
    const float4* zbase = reinterpret_cast<const float4*>(comment + (size_t)b * N * D);

    float4 aA0[4], aA1[4], aC[4];
#pragma unroll
    for (int j = 0; j < 4; j++) {
        aA0[j] = make_float4(0.f, 0.f, 0.f, 0.f);
        aA1[j] = make_float4(0.f, 0.f, 0.f, 0.f);
        aC[j]  = make_float4(0.f, 0.f, 0.f, 0.f);
    }
    float ssum = 0.f;

    for (int n = w; n < num; n += 2 * NW) {
        const bool hasB = (n + NW) < num;

        float4 zcA[4], zcB[4];
        {
            const float4* zrA = zbase + (size_t)n * (D / 4);
#pragma unroll
            for (int j = 0; j < 4; j++) zcA[j] = __ldg(&zrA[lane + 32 * j]);
        }
        if (hasB) {
            const float4* zrB = zbase + (size_t)(n + NW) * (D / 4);
#pragma unroll
            for (int j = 0; j < 4; j++) zcB[j] = __ldg(&zrB[lane + 32 * j]);
        } else {
#pragma unroll
            for (int j = 0; j < 4; j++) zcB[j] = make_float4(0.f, 0.f, 0.f, 0.f);
        }

        // ---- dots with cw0/cw1 for BOTH rows (shared LDS) ----
        float dA0 = 0.f, dA1 = 0.f, dB0 = 0.f, dB1 = 0.f;
#pragma unroll
        for (int j = 0; j < 4; j++) {
            int q = lane + 32 * j;
            float4 a = reinterpret_cast<const float4*>(sm + OFF_CW0)[q];
            float4 c = reinterpret_cast<const float4*>(sm + OFF_CW1)[q];
            dA0 = fmaf(zcA[j].x, a.x, fmaf(zcA[j].y, a.y, fmaf(zcA[j].z, a.z, fmaf(zcA[j].w, a.w, dA0))));
            dA1 = fmaf(zcA[j].x, c.x, fmaf(zcA[j].y, c.y, fmaf(zcA[j].z, c.z, fmaf(zcA[j].w, c.w, dA1))));
            dB0 = fmaf(zcB[j].x, a.x, fmaf(zcB[j].y, a.y, fmaf(zcB[j].z, a.z, fmaf(zcB[j].w, a.w, dB0))));
            dB1 = fmaf(zcB[j].x, c.x, fmaf(zcB[j].y, c.y, fmaf(zcB[j].z, c.z, fmaf(zcB[j].w, c.w, dB1))));
        }
#pragma unroll
        for (int off = 16; off; off >>= 1) {
            dA0 += __shfl_xor_sync(0xffffffffu, dA0, off);
            dA1 += __shfl_xor_sync(0xffffffffu, dA1, off);
            dB0 += __shfl_xor_sync(0xffffffffu, dB0, off);
            dB1 += __shfl_xor_sync(0xffffffffu, dB1, off);
        }
        float t0A = tanha(dA0), t1A = tanha(dA1);
        float t0B = tanha(dB0), t1B = tanha(dB1);
        if (!hasB) { t0B = 0.f; t1B = 0.f; }

        // ---- logits + accA for both rows (c0/c1 LDS shared) ----
        float lpA = 0.f, lpB = 0.f;
#pragma unroll
        for (int j = 0; j < 4; j++) {
            int q = lane + 32 * j;
            float4 c0 = reinterpret_cast<const float4*>(sm + OFF_C0)[q];
            float4 c1 = reinterpret_cast<const float4*>(sm + OFF_C1)[q];
            float zt;
            zt = tanha(fmaf(t0A, c0.x, fmaf(t1A, c1.x, zcA[j].x))); lpA = fmaf(zt, wr[j].x, lpA);
            zt = tanha(fmaf(t0B, c0.x, fmaf(t1B, c1.x, zcB[j].x))); lpB = fmaf(zt, wr[j].x, lpB);
            zt = tanha(fmaf(t0A, c0.y, fmaf(t1A, c1.y, zcA[j].y))); lpA = fmaf(zt, wr[j].y, lpA);
            zt = tanha(fmaf(t0B, c0.y, fmaf(t1B, c1.y, zcB[j].y))); lpB = fmaf(zt, wr[j].y, lpB);
            zt = tanha(fmaf(t0A, c0.z, fmaf(t1A, c1.z, zcA[j].z))); lpA = fmaf(zt, wr[j].z, lpA);
            zt = tanha(fmaf(t0B, c0.z, fmaf(t1B, c1.z, zcB[j].z))); lpB = fmaf(zt, wr[j].z, lpB);
            zt = tanha(fmaf(t0A, c0.w, fmaf(t1A, c1.w, zcA[j].w))); lpA = fmaf(zt, wr[j].w, lpA);
            zt = tanha(fmaf(t0B, c0.w, fmaf(t1B, c1.w, zcB[j].w))); lpB = fmaf(zt, wr[j].w, lpB);

            aA0[j].x = fmaf(t0A, zcA[j].x, fmaf(t0B, zcB[j].x, aA0[j].x));
            aA0[j].y = fmaf(t0A, zcA[j].y, fmaf(t0B, zcB[j].y, aA0[j].y));
            aA0[j].z = fmaf(t0A, zcA[j].z, fmaf(t0B, zcB[j].z, aA0[j].z));
            aA0[j].w = fmaf(t0A, zcA[j].w, fmaf(t0B, zcB[j].w, aA0[j].w));
            aA1[j].x = fmaf(t1A, zcA[j].x, fmaf(t1B, zcB[j].x, aA1[j].x));
            aA1[j].y = fmaf(t1A, zcA[j].y, fmaf(t1B, zcB[j].y, aA1[j].y));
            aA1[j].z = fmaf(t1A, zcA[j].z, fmaf(t1B, zcB[j].z, aA1[j].z));
            aA1[j].w = fmaf(t1A, zcA[j].w, fmaf(t1B, zcB[j].w, aA1[j].w));
        }
#pragma unroll
        for (int off = 16; off; off >>= 1) {
            lpA += __shfl_xor_sync(0xffffffffu, lpA, off);
            lpB += __shfl_xor_sync(0xffffffffu, lpB, off);
        }
        float eA = ex2(lpA);
        float eB = hasB ? ex2(lpB) : 0.f;
        ssum += eA + eB;
#pragma unroll
        for (int j = 0; j < 4; j++) {
            aC[j].x = fmaf(eA, zcA[j].x, fmaf(eB, zcB[j].x, aC[j].x));
            aC[j].y = fmaf(eA, zcA[j].y, fmaf(eB, zcB[j].y, aC[j].y));
            aC[j].z = fmaf(eA, zcA[j].z, fmaf(eB, zcB[j].z, aC[j].z));
            aC[j].w = fmaf(eA, zcA[j].w, fmaf(eB, zcB[j].w, aC[j].w));
        }
    }

    // ---- stash per-warp state (vector STS, no atomics) ----
    if (lane == 0) sm[OFF_SS + w] = ssum;
#pragma unroll
    for (int j = 0; j < 4; j++) {
        int q = lane + 32 * j;
        reinterpret_cast<float4*>(sm + OFF_BUFC + w * D)[q] = aC[j];
        reinterpret_cast<float4*>(sm + OFF_BA0 + w * D)[q]  = aA0[j];
        reinterpret_cast<float4*>(sm + OFF_BA1 + w * D)[q]  = aA1[j];
    }
    __syncthreads();

    // ---- epilogue ----
    float S = 0.f;
#pragma unroll
    for (int i = 0; i < NW; i++) S += sm[OFF_SS + i];
    float invS = __frcp_rn(S);

    float p0 = 0.f, p1 = 0.f;
    for (int d = tid; d < D; d += NT) {
        float rc = 0.f, a0 = 0.f, a1 = 0.f;
#pragma unroll
        for (int i = 0; i < NW; i++) {
            rc += sm[OFF_BUFC + i * D + d];
            a0 += sm[OFF_BA0 + i * D + d];
            a1 += sm[OFF_BA1 + i * D + d];
        }
        out[BD + (size_t)b * D + d] = rc * invS;
        float wca = __ldg(&W_ca[d]);
        p0 = fmaf(tanha(sm[OFF_C0 + d] + a0), wca, p0);
        p1 = fmaf(tanha(sm[OFF_C1 + d] + a1), wca, p1);
    }
#pragma unroll
    for (int off = 16; off; off >>= 1) {
        p0 += __shfl_xor_sync(0xffffffffu, p0, off);
        p1 += __shfl_xor_sync(0xffffffffu, p1, off);
    }
    if (lane == 0) { sm[OFF_R0 + w] = p0; sm[OFF_R1 + w] = p1; }
    __syncthreads();

    float L0 = 0.f, L1 = 0.f;
#pragma unroll
    for (int i = 0; i < NW; i++) { L0 += sm[OFF_R0 + i]; L1 += sm[OFF_R1 + i]; }
    float mm = fmaxf(L0, L1);
    float e0 = __expf(L0 - mm), e1 = __expf(L1 - mm);
    float inv2 = __frcp_rn(e0 + e1);
    float w0 = e0 * inv2, w1 = e1 * inv2;
    if (tid == 0) {
        out[2 * BD + 2 * b + 0] = w0;
        out[2 * BD + 2 * b + 1] = w1;
    }
    for (int d = tid; d < D; d += NT)
        out[(size_t)b * D + d] = fmaf(sm[OFF_C0 + d], w0, sm[OFF_C1 + d] * w1);
}

extern "C" void kernel_launch(void* const* d_in, const int* in_sizes, int n_in,
                              void* d_out, int out_size)
{
    const float* text        = (const float*)d_in[0];
    const float* img         = (const float*)d_in[1];
    const float* comment     = (const float*)d_in[2];
    const int*   comment_num = (const int*)d_in[3];
    const float* cow         = (const float*)d_in[4];
    const float* W_ca        = (const float*)d_in[5];
    // d_in[6] = b_ca: cancels in softmax
    const float* W_co        = (const float*)d_in[7];
    // d_in[8] = b_co: cancels in softmax
    float* out = (float*)d_out;

    cudaFuncSetAttribute(gemm_cw_tf32, cudaFuncAttributeMaxDynamicSharedMemorySize, GEMM_SMEM_BYTES);
    cudaFuncSetAttribute(fuse_kernel, cudaFuncAttributeMaxDynamicSharedMemorySize, SMEM_BYTES);

    dim3 g1(D / 64, (2 * B) / 64);   // (8, 64) = 512 CTAs
    gemm_cw_tf32<<<g1, 128, GEMM_SMEM_BYTES>>>(text, img, cow);
    fuse_kernel<<<B, NT, SMEM_BYTES>>>(text, img, comment, comment_num, W_ca, W_co, out);
}

// round 10
// speedup vs baseline: 1.2992x; 1.2992x over previous
#include <cuda_runtime.h>
#include <math.h>
#include <stdint.h>

#define B 2048
#define N 128
#define D 512
#define BD (B * D)
#define NW 4             // warps per CTA in fuse kernel
#define NT (NW * 32)     // 128 threads

// 8 MB scratch for cw = content @ cow, rows interleaved: row 2b = text[b]@cow, 2b+1 = img[b]@cow
__device__ float g_cw[2 * B * D];

__device__ __forceinline__ float tanha(float x) {
    float y;
    asm("tanh.approx.f32 %0, %1;" : "=f"(y) : "f"(x));
    return y;
}
__device__ __forceinline__ float ex2(float x) {
    float y;
    asm("ex2.approx.f32 %0, %1;" : "=f"(y) : "f"(x));
    return y;
}
__device__ __forceinline__ uint32_t f2tf32(float x) {
    uint32_t r;
    asm("cvt.rna.tf32.f32 %0, %1;" : "=r"(r) : "f"(x));
    return r;
}
__device__ __forceinline__ void mma_tf32(float c[4], const uint32_t a[4], const uint32_t b[2]) {
    asm volatile(
        "mma.sync.aligned.m16n8k8.row.col.f32.tf32.tf32.f32 "
        "{%0,%1,%2,%3}, {%4,%5,%6,%7}, {%8,%9}, {%0,%1,%2,%3};"
        : "+f"(c[0]), "+f"(c[1]), "+f"(c[2]), "+f"(c[3])
        : "r"(a[0]), "r"(a[1]), "r"(a[2]), "r"(a[3]), "r"(b[0]), "r"(b[1]));
}
__device__ __forceinline__ void cp_async16(void* smem_dst, const void* gmem_src) {
    uint32_t s = (uint32_t)__cvta_generic_to_shared(smem_dst);
    asm volatile("cp.async.ca.shared.global [%0], [%1], 16;" :: "r"(s), "l"(gmem_src));
}
__device__ __forceinline__ void cp_commit() {
    asm volatile("cp.async.commit_group;");
}

// ---------------------------------------------------------------------------
// Kernel 1: cw[4096,512] = A[4096,512] @ cow[512,512] via single-pass tf32
// mma.sync (tolerance analysis: dot outputs sit deep in tanh saturation, so
// tf32 rounding error ~5e-4 on inputs propagates to ~1e-4 overall).
// Tile M=64 N=128 K=32; grid 256 CTAs; 2-stage cp.async double buffering.
// ---------------------------------------------------------------------------
#define GM_KT 32
#define AST 36     // A row stride (floats): [m][k] padded
#define WST 132    // W row stride (floats): [k][n] padded
#define A_STAGE (64 * AST)
#define W_STAGE (GM_KT * WST)
#define GEMM_SMEM_BYTES ((2 * A_STAGE + 2 * W_STAGE) * 4)

__global__ __launch_bounds__(256) void gemm_cw_tf32(
    const float* __restrict__ text,
    const float* __restrict__ img,
    const float* __restrict__ cow)
{
    extern __shared__ float gsm[];
    float* As = gsm;                     // 2 stages of [64][AST]
    float* Ws = gsm + 2 * A_STAGE;       // 2 stages of [GM_KT][WST]

    const int t = threadIdx.x;
    const int wid = t >> 5;
    const int lane = t & 31;
    const int warp_m = (wid & 1) * 32;
    const int warp_n = (wid >> 1) * 32;
    const int brow = blockIdx.y * 64;
    const int bcol = blockIdx.x * 128;
    const int g  = lane >> 2;   // 0..7
    const int tg = lane & 3;    // 0..3

    float c[2][4][4];
#pragma unroll
    for (int mi = 0; mi < 2; mi++)
#pragma unroll
        for (int ni = 0; ni < 4; ni++)
#pragma unroll
            for (int j = 0; j < 4; j++) c[mi][ni][j] = 0.f;

    auto load_stage = [&](int st, int k0) {
#pragma unroll
        for (int s = 0; s < 2; s++) {               // A: 512 x 16B / 256 thr
            int f = t + 256 * s;
            int r = f >> 3;
            int kk = (f & 7) * 4;
            int gr = brow + r;
            const float* src = ((gr & 1) ? img : text) + (size_t)(gr >> 1) * D + k0 + kk;
            cp_async16(&As[st * A_STAGE + r * AST + kk], src);
        }
#pragma unroll
        for (int s = 0; s < 4; s++) {               // W: 1024 x 16B / 256 thr
            int f = t + 256 * s;
            int kk = f >> 5;
            int n = (f & 31) * 4;
            const float* src = cow + (size_t)(k0 + kk) * D + bcol + n;
            cp_async16(&Ws[st * W_STAGE + kk * WST + n], src);
        }
    };

    const int NKT = D / GM_KT;   // 16
    load_stage(0, 0);
    cp_commit();

    for (int kt = 0; kt < NKT; kt++) {
        if (kt + 1 < NKT) {
            load_stage((kt + 1) & 1, (kt + 1) * GM_KT);
            cp_commit();
            asm volatile("cp.async.wait_group 1;");
        } else {
            asm volatile("cp.async.wait_group 0;");
        }
        __syncthreads();

        const float* Ab = As + (kt & 1) * A_STAGE;
        const float* Wb = Ws + (kt & 1) * W_STAGE;

#pragma unroll
        for (int k8 = 0; k8 < GM_KT; k8 += 8) {
            uint32_t ahi[2][4];
#pragma unroll
            for (int mi = 0; mi < 2; mi++) {
                int r0 = warp_m + mi * 16;
                ahi[mi][0] = f2tf32(Ab[(r0 + g)     * AST + k8 + tg]);
                ahi[mi][1] = f2tf32(Ab[(r0 + 8 + g) * AST + k8 + tg]);
                ahi[mi][2] = f2tf32(Ab[(r0 + g)     * AST + k8 + tg + 4]);
                ahi[mi][3] = f2tf32(Ab[(r0 + 8 + g) * AST + k8 + tg + 4]);
            }
            uint32_t bhi[4][2];
#pragma unroll
            for (int ni = 0; ni < 4; ni++) {
                int n0 = warp_n + ni * 8;
                bhi[ni][0] = f2tf32(Wb[(k8 + tg)     * WST + n0 + g]);
                bhi[ni][1] = f2tf32(Wb[(k8 + tg + 4) * WST + n0 + g]);
            }
#pragma unroll
            for (int mi = 0; mi < 2; mi++)
#pragma unroll
                for (int ni = 0; ni < 4; ni++)
                    mma_tf32(c[mi][ni], ahi[mi], bhi[ni]);
        }
        __syncthreads();
    }

#pragma unroll
    for (int mi = 0; mi < 2; mi++)
#pragma unroll
        for (int ni = 0; ni < 4; ni++) {
            int row = brow + warp_m + mi * 16 + g;
            int col = bcol + warp_n + ni * 8 + 2 * tg;
            float2 v0 = make_float2(c[mi][ni][0], c[mi][ni][1]);
            float2 v1 = make_float2(c[mi][ni][2], c[mi][ni][3]);
            *reinterpret_cast<float2*>(&g_cw[(size_t)row * D + col]) = v0;
            *reinterpret_cast<float2*>(&g_cw[(size_t)(row + 8) * D + col]) = v1;
        }
}

// Dynamic SMEM layout for fuse kernel (floats).
// The cp.async z-ring ALIASES the epilogue per-warp buffers (ring is dead
// after the mainloop; guarded by wait_group 0 + __syncthreads).
#define OFF_CW0  0
#define OFF_CW1  (OFF_CW0 + D)
#define OFF_C0   (OFF_CW1 + D)
#define OFF_C1   (OFF_C0 + D)
#define OFF_RING (OFF_C1 + D)                 // NW*2 slots * 2 rows * D floats
#define RING_FLOATS (NW * 2 * 2 * D)          // 8192
#define OFF_BUFC OFF_RING                     // aliased: NW*D
#define OFF_BA0  (OFF_BUFC + NW * D)
#define OFF_BA1  (OFF_BA0 + NW * D)
#define OFF_SS   (OFF_RING + RING_FLOATS)
#define OFF_R0   (OFF_SS + NW)
#define OFF_R1   (OFF_R0 + NW)
#define SMEM_FLOATS (OFF_R1 + NW)
#define SMEM_BYTES  (SMEM_FLOATS * 4)

// ---------------------------------------------------------------------------
// Kernel 2: one CTA (4 warps, 128 thr, <=128 regs, 4 CTAs/SM) per sample.
// Warp w processes row PAIRS (n, n+NW). z is staged through a per-warp
// cp.async ring of depth 2 pairs (4 rows ~ 2400 cyc in flight) so DRAM
// latency is never exposed. Each lane reads back exactly the 16B chunks it
// wrote (no warp sync needed). Uniform commit-group counting (empty commits
// for out-of-range rows). No atomics; branchless unshifted softmax.
// ---------------------------------------------------------------------------
__global__ __launch_bounds__(NT, 4) void fuse_kernel(
    const float* __restrict__ text,
    const float* __restrict__ img,
    const float* __restrict__ comment,
    const int*   __restrict__ comment_num,
    const float* __restrict__ W_ca,
    const float* __restrict__ W_co,
    float* __restrict__ out)
{
    extern __shared__ float sm[];
    const int b = blockIdx.x;
    const int tid = threadIdx.x;
    const int w = tid >> 5;
    const int lane = tid & 31;

    for (int d = tid; d < D; d += NT) {
        sm[OFF_CW0 + d] = g_cw[(size_t)(2 * b) * D + d];
        sm[OFF_CW1 + d] = g_cw[(size_t)(2 * b + 1) * D + d];
        sm[OFF_C0 + d]  = text[(size_t)b * D + d];
        sm[OFF_C1 + d]  = img[(size_t)b * D + d];
    }
    __syncthreads();

    const float LOG2E = 1.4426950408889634f;
    float4 wr[4];
#pragma unroll
    for (int j = 0; j < 4; j++) {
        float4 wv = __ldg(&reinterpret_cast<const float4*>(W_co)[lane + 32 * j]);
        wr[j] = make_float4(wv.x * LOG2E, wv.y * LOG2E, wv.z * LOG2E, wv.w * LOG2E);
    }

    const int num = comment_num[b];
    const float4* zbase = reinterpret_cast<const float4*>(comment + (size_t)b * N * D);

    float4 aA0[4], aA1[4], aC[4];
#pragma unroll
    for (int j = 0; j < 4; j++) {
        aA0[j] = make_float4(0.f, 0.f, 0.f, 0.f);
        aA1[j] = make_float4(0.f, 0.f, 0.f, 0.f);
        aC[j]  = make_float4(0.f, 0.f, 0.f, 0.f);
    }
    float ssum = 0.f;

    // Issue one pair (rows n0, n0+NW) into ring slot; ALWAYS commits exactly
    // one group so wait_group counting stays uniform.
    auto issue_pair = [&](int slot, int n0) {
        float* rb = sm + OFF_RING + (size_t)(w * 4 + slot * 2) * D;
        if (n0 < num) {
            const float4* src = zbase + (size_t)n0 * (D / 4);
#pragma unroll
            for (int j = 0; j < 4; j++) {
                int q = lane + 32 * j;
                cp_async16(rb + q * 4, src + q);
            }
        }
        if (n0 + NW < num) {
            const float4* src = zbase + (size_t)(n0 + NW) * (D / 4);
#pragma unroll
            for (int j = 0; j < 4; j++) {
                int q = lane + 32 * j;
                cp_async16(rb + D + q * 4, src + q);
            }
        }
        cp_commit();
    };

    issue_pair(0, w);
    issue_pair(1, w + 2 * NW);

    int p = 0;
    for (int n = w; n < num; n += 2 * NW, p ^= 1) {
        asm volatile("cp.async.wait_group 1;");
        const bool hasB = (n + NW) < num;
        const float4* rb = reinterpret_cast<const float4*>(sm + OFF_RING + (size_t)(w * 4 + p * 2) * D);

        float4 zcA[4], zcB[4];
#pragma unroll
        for (int j = 0; j < 4; j++) zcA[j] = rb[lane + 32 * j];
        if (hasB) {
#pragma unroll
            for (int j = 0; j < 4; j++) zcB[j] = rb[D / 4 + lane + 32 * j];
        } else {
#pragma unroll
            for (int j = 0; j < 4; j++) zcB[j] = make_float4(0.f, 0.f, 0.f, 0.f);
        }

        // refill this slot with the pair 2 ahead (commit is unconditional)
        issue_pair(p, n + 4 * NW);

        // ---- dots with cw0/cw1 for BOTH rows (shared LDS) ----
        float dA0 = 0.f, dA1 = 0.f, dB0 = 0.f, dB1 = 0.f;
#pragma unroll
        for (int j = 0; j < 4; j++) {
            int q = lane + 32 * j;
            float4 a = reinterpret_cast<const float4*>(sm + OFF_CW0)[q];
            float4 c = reinterpret_cast<const float4*>(sm + OFF_CW1)[q];
            dA0 = fmaf(zcA[j].x, a.x, fmaf(zcA[j].y, a.y, fmaf(zcA[j].z, a.z, fmaf(zcA[j].w, a.w, dA0))));
            dA1 = fmaf(zcA[j].x, c.x, fmaf(zcA[j].y, c.y, fmaf(zcA[j].z, c.z, fmaf(zcA[j].w, c.w, dA1))));
            dB0 = fmaf(zcB[j].x, a.x, fmaf(zcB[j].y, a.y, fmaf(zcB[j].z, a.z, fmaf(zcB[j].w, a.w, dB0))));
            dB1 = fmaf(zcB[j].x, c.x, fmaf(zcB[j].y, c.y, fmaf(zcB[j].z, c.z, fmaf(zcB[j].w, c.w, dB1))));
        }
#pragma unroll
        for (int off = 16; off; off >>= 1) {
            dA0 += __shfl_xor_sync(0xffffffffu, dA0, off);
            dA1 += __shfl_xor_sync(0xffffffffu, dA1, off);
            dB0 += __shfl_xor_sync(0xffffffffu, dB0, off);
            dB1 += __shfl_xor_sync(0xffffffffu, dB1, off);
        }
        float t0A = tanha(dA0), t1A = tanha(dA1);
        float t0B = tanha(dB0), t1B = tanha(dB1);
        if (!hasB) { t0B = 0.f; t1B = 0.f; }

        // ---- logits + accA for both rows (c0/c1 LDS shared) ----
        float lpA = 0.f, lpB = 0.f;
#pragma unroll
        for (int j = 0; j < 4; j++) {
            int q = lane + 32 * j;
            float4 c0 = reinterpret_cast<const float4*>(sm + OFF_C0)[q];
            float4 c1 = reinterpret_cast<const float4*>(sm + OFF_C1)[q];
            float zt;
            zt = tanha(fmaf(t0A, c0.x, fmaf(t1A, c1.x, zcA[j].x))); lpA = fmaf(zt, wr[j].x, lpA);
            zt = tanha(fmaf(t0B, c0.x, fmaf(t1B, c1.x, zcB[j].x))); lpB = fmaf(zt, wr[j].x, lpB);
            zt = tanha(fmaf(t0A, c0.y, fmaf(t1A, c1.y, zcA[j].y))); lpA = fmaf(zt, wr[j].y, lpA);
            zt = tanha(fmaf(t0B, c0.y, fmaf(t1B, c1.y, zcB[j].y))); lpB = fmaf(zt, wr[j].y, lpB);
            zt = tanha(fmaf(t0A, c0.z, fmaf(t1A, c1.z, zcA[j].z))); lpA = fmaf(zt, wr[j].z, lpA);
            zt = tanha(fmaf(t0B, c0.z, fmaf(t1B, c1.z, zcB[j].z))); lpB = fmaf(zt, wr[j].z, lpB);
            zt = tanha(fmaf(t0A, c0.w, fmaf(t1A, c1.w, zcA[j].w))); lpA = fmaf(zt, wr[j].w, lpA);
            zt = tanha(fmaf(t0B, c0.w, fmaf(t1B, c1.w, zcB[j].w))); lpB = fmaf(zt, wr[j].w, lpB);

            aA0[j].x = fmaf(t0A, zcA[j].x, fmaf(t0B, zcB[j].x, aA0[j].x));
            aA0[j].y = fmaf(t0A, zcA[j].y, fmaf(t0B, zcB[j].y, aA0[j].y));
            aA0[j].z = fmaf(t0A, zcA[j].z, fmaf(t0B, zcB[j].z, aA0[j].z));
            aA0[j].w = fmaf(t0A, zcA[j].w, fmaf(t0B, zcB[j].w, aA0[j].w));
            aA1[j].x = fmaf(t1A, zcA[j].x, fmaf(t1B, zcB[j].x, aA1[j].x));
            aA1[j].y = fmaf(t1A, zcA[j].y, fmaf(t1B, zcB[j].y, aA1[j].y));
            aA1[j].z = fmaf(t1A, zcA[j].z, fmaf(t1B, zcB[j].z, aA1[j].z));
            aA1[j].w = fmaf(t1A, zcA[j].w, fmaf(t1B, zcB[j].w, aA1[j].w));
        }
#pragma unroll
        for (int off = 16; off; off >>= 1) {
            lpA += __shfl_xor_sync(0xffffffffu, lpA, off);
            lpB += __shfl_xor_sync(0xffffffffu, lpB, off);
        }
        float eA = ex2(lpA);
        float eB = hasB ? ex2(lpB) : 0.f;
        ssum += eA + eB;
#pragma unroll
        for (int j = 0; j < 4; j++) {
            aC[j].x = fmaf(eA, zcA[j].x, fmaf(eB, zcB[j].x, aC[j].x));
            aC[j].y = fmaf(eA, zcA[j].y, fmaf(eB, zcB[j].y, aC[j].y));
            aC[j].z = fmaf(eA, zcA[j].z, fmaf(eB, zcB[j].z, aC[j].z));
            aC[j].w = fmaf(eA, zcA[j].w, fmaf(eB, zcB[j].w, aC[j].w));
        }
    }

    // All ring traffic must be drained before the region is reused as the
    // epilogue buffers (BUFC/BA0/BA1 alias the ring across warps).
    asm volatile("cp.async.wait_group 0;");
    __syncthreads();

    if (lane == 0) sm[OFF_SS + w] = ssum;
#pragma unroll
    for (int j = 0; j < 4; j++) {
        int q = lane + 32 * j;
        reinterpret_cast<float4*>(sm + OFF_BUFC + w * D)[q] = aC[j];
        reinterpret_cast<float4*>(sm + OFF_BA0 + w * D)[q]  = aA0[j];
        reinterpret_cast<float4*>(sm + OFF_BA1 + w * D)[q]  = aA1[j];
    }
    __syncthreads();

    // ---- epilogue ----
    float S = 0.f;
#pragma unroll
    for (int i = 0; i < NW; i++) S += sm[OFF_SS + i];
    float invS = __frcp_rn(S);

    float p0 = 0.f, p1 = 0.f;
    for (int d = tid; d < D; d += NT) {
        float rc = 0.f, a0 = 0.f, a1 = 0.f;
#pragma unroll
        for (int i = 0; i < NW; i++) {
            rc += sm[OFF_BUFC + i * D + d];
            a0 += sm[OFF_BA0 + i * D + d];
            a1 += sm[OFF_BA1 + i * D + d];
        }
        out[BD + (size_t)b * D + d] = rc * invS;
        float wca = __ldg(&W_ca[d]);
        p0 = fmaf(tanha(sm[OFF_C0 + d] + a0), wca, p0);
        p1 = fmaf(tanha(sm[OFF_C1 + d] + a1), wca, p1);
    }
#pragma unroll
    for (int off = 16; off; off >>= 1) {
        p0 += __shfl_xor_sync(0xffffffffu, p0, off);
        p1 += __shfl_xor_sync(0xffffffffu, p1, off);
    }
    if (lane == 0) { sm[OFF_R0 + w] = p0; sm[OFF_R1 + w] = p1; }
    __syncthreads();

    float L0 = 0.f, L1 = 0.f;
#pragma unroll
    for (int i = 0; i < NW; i++) { L0 += sm[OFF_R0 + i]; L1 += sm[OFF_R1 + i]; }
    float mm = fmaxf(L0, L1);
    float e0 = __expf(L0 - mm), e1 = __expf(L1 - mm);
    float inv2 = __frcp_rn(e0 + e1);
    float w0 = e0 * inv2, w1 = e1 * inv2;
    if (tid == 0) {
        out[2 * BD + 2 * b + 0] = w0;
        out[2 * BD + 2 * b + 1] = w1;
    }
    for (int d = tid; d < D; d += NT)
        out[(size_t)b * D + d] = fmaf(sm[OFF_C0 + d], w0, sm[OFF_C1 + d] * w1);
}

extern "C" void kernel_launch(void* const* d_in, const int* in_sizes, int n_in,
                              void* d_out, int out_size)
{
    const float* text        = (const float*)d_in[0];
    const float* img         = (const float*)d_in[1];
    const float* comment     = (const float*)d_in[2];
    const int*   comment_num = (const int*)d_in[3];
    const float* cow         = (const float*)d_in[4];
    const float* W_ca        = (const float*)d_in[5];
    // d_in[6] = b_ca: cancels in softmax
    const float* W_co        = (const float*)d_in[7];
    // d_in[8] = b_co: cancels in softmax
    float* out = (float*)d_out;

    cudaFuncSetAttribute(gemm_cw_tf32, cudaFuncAttributeMaxDynamicSharedMemorySize, GEMM_SMEM_BYTES);
    cudaFuncSetAttribute(fuse_kernel, cudaFuncAttributeMaxDynamicSharedMemorySize, SMEM_BYTES);

    dim3 g1(D / 128, (2 * B) / 64);   // (4, 64) = 256 CTAs
    gemm_cw_tf32<<<g1, 256, GEMM_SMEM_BYTES>>>(text, img, cow);
    fuse_kernel<<<B, NT, SMEM_BYTES>>>(text, img, comment, comment_num, W_ca, W_co, out);
}